// round 6
// baseline (speedup 1.0000x reference)
#include <cuda_runtime.h>
#include <cuda_bf16.h>
#include <cstdint>

// ---------------------------------------------------------------------------
// GNNRepresentationNetwork  B=16, C=16, N=4096 (64x64), D_E=64, D_H=128, D_R=256
// embed: FFMA2 fused MLP (fp32 exact, round-3 best).
// GCN layers: warp-level mma.sync bf16 (HMMA), 3-pass split:
//   D = Ah*Bh + Ah*Bl + Al*Bh  with  x = hi(bf16) + lo(bf16), fp32 accum.
//   D(128d x 128n) = W^T(128 x K) * stencil(K x 128n), K in {64,128}
// GCN identity (exact): relu(A(hW+b)) = relu((A h)W + s_n b), s_n = deg/(deg+1e-6)
// ---------------------------------------------------------------------------

#define B_  16
#define N_  4096

typedef unsigned long long u64;

__device__ float g_bufA[B_ * 128 * N_];
__device__ float g_bufB[B_ * 128 * N_];
__device__ float g_part[B_ * 32 * 128];

__device__ __forceinline__ void fma2(u64& d, u64 a, u64 b) {
    asm("fma.rn.f32x2 %0, %1, %2, %0;" : "+l"(d) : "l"(a), "l"(b));
}
__device__ __forceinline__ u64 pack2(float lo, float hi) {
    u64 r; asm("mov.b64 %0, {%1, %2};" : "=l"(r) : "f"(lo), "f"(hi)); return r;
}
__device__ __forceinline__ float2 unpack2(u64 v) {
    float2 f; asm("mov.b64 {%0, %1}, %2;" : "=f"(f.x), "=f"(f.y) : "l"(v)); return f;
}
__device__ __forceinline__ float recip_deg(int deg) {
    return deg == 4 ? 0.2499999375f : (deg == 3 ? 0.3333332222f : 0.4999997500f);
}
__device__ __forceinline__ uint32_t pack_bf16(__nv_bfloat16 a, __nv_bfloat16 b) {
    return (uint32_t)__bfloat16_as_ushort(a) | ((uint32_t)__bfloat16_as_ushort(b) << 16);
}
__device__ __forceinline__ void mma_bf16(float* c, const uint32_t* a, uint32_t b0, uint32_t b1) {
    asm volatile(
        "mma.sync.aligned.m16n8k16.row.col.f32.bf16.bf16.f32 "
        "{%0,%1,%2,%3}, {%4,%5,%6,%7}, {%8,%9}, {%0,%1,%2,%3};"
        : "+f"(c[0]), "+f"(c[1]), "+f"(c[2]), "+f"(c[3])
        : "r"(a[0]), "r"(a[1]), "r"(a[2]), "r"(a[3]), "r"(b0), "r"(b1));
}

// ---------------------------------------------------------------------------
// GCN layer via mma.sync.  Per CTA: D(128d x 128n).  8 warps x (16d x 128n).
// smem (dynamic): scp[128] f32 | Ls 16x256 f32 | Wh | Wl | Sh | Sl
//   W*,S*: 128 rows x (K/2+1) words (bf16 pairs, k contiguous; odd word stride)
// MEAN: per-block partial sums of relu'd outputs instead of store.
// ---------------------------------------------------------------------------
template <int K, bool MEAN>
__global__ void __launch_bounds__(256)
gcn_mma_kernel(const float* __restrict__ in, const float* __restrict__ Wt,
               const float* __restrict__ bias, float* __restrict__ out,
               float* __restrict__ part)
{
    constexpr int RW   = K / 2 + 1;        // words per row (odd)
    constexpr int ROWB = RW * 4;           // bytes per row
    constexpr int OFF_LS = 512;
    constexpr int OFF_WH = OFF_LS + 16384;
    constexpr int OFF_WL = OFF_WH + 128 * ROWB;
    constexpr int OFF_SH = OFF_WL + 128 * ROWB;
    constexpr int OFF_SL = OFF_SH + 128 * ROWB;

    extern __shared__ __align__(16) char smem[];
    float* scp = reinterpret_cast<float*>(smem);
    float* Ls  = reinterpret_cast<float*>(smem + OFF_LS);

    const int tid = threadIdx.x;
    const int m0 = blockIdx.x * 128;
    const int b  = m0 >> 12, n0 = m0 & (N_ - 1);
    const float* inb = in + (size_t)b * K * N_;

    // --- sc table ---
    if (tid < 128) {
        const int nn = n0 + tid;
        const int gi = nn >> 6, gj = nn & 63;
        const float fd = (float)((gi > 0) + (gi < 63) + (gj > 0) + (gj < 63));
        scp[tid] = fd / (fd + 1e-6f);
    }

    // --- Stage W^T split (A operand): rows = d, cols = k contiguous ---
    for (int i = tid; i < K * 128; i += 256) {
        const int k = i >> 7, d = i & 127;          // Wt is [K][128]
        const float w = Wt[i];
        const __nv_bfloat16 h = __float2bfloat16(w);
        const __nv_bfloat16 l = __float2bfloat16(w - __bfloat162float(h));
        const int off = d * ROWB + k * 2;
        *reinterpret_cast<__nv_bfloat16*>(smem + OFF_WH + off) = h;
        *reinterpret_cast<__nv_bfloat16*>(smem + OFF_WL + off) = l;
    }

    // --- Build stencil operand S (rows = n, cols = k contiguous), split ---
    {
        const int n  = tid & 127;
        const int k8 = (tid >> 7) * 8;
        const int gn = n0 + n, gj = gn & 63;
        const bool lv = gj != 0, rv = gj != 63;
        const int dm = ((gn >= 64) ? 1 : 0) + ((gn < N_ - 64) ? 1 : 0);
        const float rd = recip_deg(dm + (lv ? 1 : 0) + (rv ? 1 : 0));

        for (int kc = 0; kc < K; kc += 16) {
            // stage halo window: 16 rows x 256 floats (zero-padded ends)
#pragma unroll
            for (int i = 0; i < 4; i++) {
                const int idx = i * 256 + tid;
                const int r = idx >> 6, c4 = idx & 63;
                const int nw = n0 - 64 + c4 * 4;
                float4 v = make_float4(0.f, 0.f, 0.f, 0.f);
                if (nw >= 0 && nw < N_)
                    v = *reinterpret_cast<const float4*>(inb + (size_t)(kc + r) * N_ + nw);
                *reinterpret_cast<float4*>(&Ls[r * 256 + c4 * 4]) = v;
            }
            __syncthreads();

            uint32_t hw[4], lw[4];
#pragma unroll
            for (int p = 0; p < 4; p++) {
                __nv_bfloat16 h2[2], l2[2];
#pragma unroll
                for (int e = 0; e < 2; e++) {
                    const float* L = &Ls[(k8 + p * 2 + e) * 256];
                    const float o = (L[n] + L[n + 128]
                                     + (lv ? L[n + 63] : 0.f)
                                     + (rv ? L[n + 65] : 0.f)) * rd;
                    h2[e] = __float2bfloat16(o);
                    l2[e] = __float2bfloat16(o - __bfloat162float(h2[e]));
                }
                hw[p] = pack_bf16(h2[0], h2[1]);
                lw[p] = pack_bf16(l2[0], l2[1]);
            }
            const int woff = n * ROWB + (kc + k8) * 2;   // byte offset (4B aligned)
#pragma unroll
            for (int p = 0; p < 4; p++) {
                *reinterpret_cast<uint32_t*>(smem + OFF_SH + woff + p * 4) = hw[p];
                *reinterpret_cast<uint32_t*>(smem + OFF_SL + woff + p * 4) = lw[p];
            }
            __syncthreads();
        }
    }

    // --- MMA mainloop: warp w -> d rows [w*16, w*16+16), all 128 n ---
    const int wid = tid >> 5, lane = tid & 31;
    const int grp = lane >> 2, tig = lane & 3;
    const int db = wid * 16;

    float acc[16][4];
#pragma unroll
    for (int c = 0; c < 16; c++)
#pragma unroll
        for (int j = 0; j < 4; j++) acc[c][j] = 0.f;

    const char* whr0 = smem + OFF_WH + (db + grp) * ROWB;
    const char* whr1 = whr0 + 8 * ROWB;
    const char* wlr0 = smem + OFF_WL + (db + grp) * ROWB;
    const char* wlr1 = wlr0 + 8 * ROWB;

#pragma unroll
    for (int ks = 0; ks < K / 16; ks++) {
        const int koff = ks * 32 + tig * 4;          // byte offset of k = ks*16 + tig*2
        uint32_t ah[4], al[4];
        ah[0] = *reinterpret_cast<const uint32_t*>(whr0 + koff);
        ah[1] = *reinterpret_cast<const uint32_t*>(whr1 + koff);
        ah[2] = *reinterpret_cast<const uint32_t*>(whr0 + koff + 16);
        ah[3] = *reinterpret_cast<const uint32_t*>(whr1 + koff + 16);
        al[0] = *reinterpret_cast<const uint32_t*>(wlr0 + koff);
        al[1] = *reinterpret_cast<const uint32_t*>(wlr1 + koff);
        al[2] = *reinterpret_cast<const uint32_t*>(wlr0 + koff + 16);
        al[3] = *reinterpret_cast<const uint32_t*>(wlr1 + koff + 16);
#pragma unroll
        for (int c = 0; c < 16; c++) {
            const char* sh = smem + OFF_SH + (c * 8 + grp) * ROWB + koff;
            const char* sl = smem + OFF_SL + (c * 8 + grp) * ROWB + koff;
            const uint32_t bh0 = *reinterpret_cast<const uint32_t*>(sh);
            const uint32_t bh1 = *reinterpret_cast<const uint32_t*>(sh + 16);
            const uint32_t bl0 = *reinterpret_cast<const uint32_t*>(sl);
            const uint32_t bl1 = *reinterpret_cast<const uint32_t*>(sl + 16);
            mma_bf16(acc[c], ah, bh0, bh1);
            mma_bf16(acc[c], ah, bl0, bl1);
            mma_bf16(acc[c], al, bh0, bh1);
        }
    }

    // --- Epilogue: scaled bias + relu ---
    const float bv0 = __ldg(&bias[db + grp]);
    const float bv1 = __ldg(&bias[db + grp + 8]);

    if (!MEAN) {
        float* o0 = out + (size_t)b * 128 * N_ + (size_t)(db + grp) * N_ + n0;
        float* o1 = o0 + (size_t)8 * N_;
#pragma unroll
        for (int c = 0; c < 16; c++) {
            const int nn = c * 8 + tig * 2;
            const float s0 = scp[nn], s1 = scp[nn + 1];
            float2 r0, r1;
            r0.x = fmaxf(fmaf(s0, bv0, acc[c][0]), 0.f);
            r0.y = fmaxf(fmaf(s1, bv0, acc[c][1]), 0.f);
            r1.x = fmaxf(fmaf(s0, bv1, acc[c][2]), 0.f);
            r1.y = fmaxf(fmaf(s1, bv1, acc[c][3]), 0.f);
            *reinterpret_cast<float2*>(o0 + nn) = r0;
            *reinterpret_cast<float2*>(o1 + nn) = r1;
        }
    } else {
        float s0 = 0.f, s1 = 0.f;
#pragma unroll
        for (int c = 0; c < 16; c++) {
            const int nn = c * 8 + tig * 2;
            const float sa = scp[nn], sb = scp[nn + 1];
            s0 += fmaxf(fmaf(sa, bv0, acc[c][0]), 0.f) + fmaxf(fmaf(sb, bv0, acc[c][1]), 0.f);
            s1 += fmaxf(fmaf(sa, bv1, acc[c][2]), 0.f) + fmaxf(fmaf(sb, bv1, acc[c][3]), 0.f);
        }
        // reduce over tig (4 lanes)
        s0 += __shfl_xor_sync(0xffffffffu, s0, 1);
        s0 += __shfl_xor_sync(0xffffffffu, s0, 2);
        s1 += __shfl_xor_sync(0xffffffffu, s1, 1);
        s1 += __shfl_xor_sync(0xffffffffu, s1, 2);
        if (tig == 0) {
            part[(size_t)blockIdx.x * 128 + db + grp]     = s0;
            part[(size_t)blockIdx.x * 128 + db + grp + 8] = s1;
        }
    }
}

// ---------------------------------------------------------------------------
// Fused embed MLP (round-3 FFMA2 version): out = relu(relu(x W1 + b1) W2 + b2)
// ---------------------------------------------------------------------------
__global__ void __launch_bounds__(256)
embed_kernel(const float* __restrict__ obs,
             const float* __restrict__ w1, const float* __restrict__ b1,
             const float* __restrict__ w2, const float* __restrict__ b2,
             float* __restrict__ out)
{
    __shared__ __align__(16) float Xs[16 * 128];
    __shared__ __align__(16) float Ws[16 * 64];
    __shared__ __align__(16) float Hs[64 * 128];

    const int tid = threadIdx.x, tx = tid & 15, ty = tid >> 4;
    const int m0 = blockIdx.x * 128;
    const int b  = m0 >> 12, n0 = m0 & (N_ - 1);
    const float* xb = obs + (size_t)b * 16 * N_ + n0;

    {
        const int i0 = tid, i1 = tid + 256;
        *reinterpret_cast<float4*>(&Xs[(i0 >> 5) * 128 + (i0 & 31) * 4]) =
            *(reinterpret_cast<const float4*>(xb + (size_t)(i0 >> 5) * N_) + (i0 & 31));
        *reinterpret_cast<float4*>(&Xs[(i1 >> 5) * 128 + (i1 & 31) * 4]) =
            *(reinterpret_cast<const float4*>(xb + (size_t)(i1 >> 5) * N_) + (i1 & 31));
    }
    *reinterpret_cast<float4*>(&Ws[tid * 4]) = *(reinterpret_cast<const float4*>(w1) + tid);
    __syncthreads();

    u64 acc[4][4];
#pragma unroll
    for (int dd = 0; dd < 4; dd++) {
        const float bv = b1[ty * 4 + dd];
        const u64 bp = pack2(bv, bv);
#pragma unroll
        for (int j = 0; j < 4; j++) acc[dd][j] = bp;
    }
#pragma unroll
    for (int k = 0; k < 16; k++) {
        const ulonglong2 a01 = *reinterpret_cast<const ulonglong2*>(&Xs[k * 128 + tx * 8]);
        const ulonglong2 a23 = *reinterpret_cast<const ulonglong2*>(&Xs[k * 128 + tx * 8 + 4]);
        const u64 a[4] = { a01.x, a01.y, a23.x, a23.y };
        const float4 w = *reinterpret_cast<const float4*>(&Ws[k * 64 + ty * 4]);
        const float wv[4] = { w.x, w.y, w.z, w.w };
#pragma unroll
        for (int dd = 0; dd < 4; dd++) {
            const u64 wd = pack2(wv[dd], wv[dd]);
#pragma unroll
            for (int j = 0; j < 4; j++) fma2(acc[dd][j], wd, a[j]);
        }
    }
#pragma unroll
    for (int dd = 0; dd < 4; dd++) {
        float* hr = &Hs[(ty * 4 + dd) * 128 + tx * 8];
#pragma unroll
        for (int j = 0; j < 4; j += 2) {
            const float2 p0 = unpack2(acc[dd][j]), p1 = unpack2(acc[dd][j + 1]);
            float4 o = { fmaxf(p0.x, 0.f), fmaxf(p0.y, 0.f), fmaxf(p1.x, 0.f), fmaxf(p1.y, 0.f) };
            *reinterpret_cast<float4*>(hr + j * 2) = o;
        }
    }
    __syncthreads();

    u64 acc2[4][4];
#pragma unroll
    for (int dd = 0; dd < 4; dd++) {
        const float bv = b2[ty * 4 + dd];
        const u64 bp = pack2(bv, bv);
#pragma unroll
        for (int j = 0; j < 4; j++) acc2[dd][j] = bp;
    }
    for (int kc = 0; kc < 64; kc += 16) {
        __syncthreads();
        *reinterpret_cast<float4*>(&Ws[tid * 4]) =
            *(reinterpret_cast<const float4*>(w2 + kc * 64) + tid);
        __syncthreads();
#pragma unroll
        for (int k = 0; k < 16; k++) {
            const ulonglong2 a01 = *reinterpret_cast<const ulonglong2*>(&Hs[(kc + k) * 128 + tx * 8]);
            const ulonglong2 a23 = *reinterpret_cast<const ulonglong2*>(&Hs[(kc + k) * 128 + tx * 8 + 4]);
            const u64 a[4] = { a01.x, a01.y, a23.x, a23.y };
            const float4 w = *reinterpret_cast<const float4*>(&Ws[k * 64 + ty * 4]);
            const float wv[4] = { w.x, w.y, w.z, w.w };
#pragma unroll
            for (int dd = 0; dd < 4; dd++) {
                const u64 wd = pack2(wv[dd], wv[dd]);
#pragma unroll
                for (int j = 0; j < 4; j++) fma2(acc2[dd][j], wd, a[j]);
            }
        }
    }

    float* ob = out + (size_t)b * 64 * N_ + n0 + tx * 8;
#pragma unroll
    for (int dd = 0; dd < 4; dd++) {
        float* orow = ob + (size_t)(ty * 4 + dd) * N_;
#pragma unroll
        for (int j = 0; j < 4; j += 2) {
            const float2 p0 = unpack2(acc2[dd][j]), p1 = unpack2(acc2[dd][j + 1]);
            float4 o = { fmaxf(p0.x, 0.f), fmaxf(p0.y, 0.f), fmaxf(p1.x, 0.f), fmaxf(p1.y, 0.f) };
            *reinterpret_cast<float4*>(orow + j * 2) = o;
        }
    }
}

// ---------------------------------------------------------------------------
// Readout: g[b] = mean partials; out = relu(relu(g r1 + b1) r2 + b2)
// ---------------------------------------------------------------------------
__global__ void __launch_bounds__(256)
readout_kernel(const float* __restrict__ part,
               const float* __restrict__ r1w, const float* __restrict__ r1b,
               const float* __restrict__ r2w, const float* __restrict__ r2b,
               float* __restrict__ out)
{
    __shared__ float gs[128];
    __shared__ float ts[256];
    const int b = blockIdx.x, t = threadIdx.x;

    if (t < 128) {
        float s = 0.f;
        const float* p = part + (size_t)b * 32 * 128 + t;
#pragma unroll
        for (int k = 0; k < 32; k++) s += p[k * 128];
        gs[t] = s * (1.0f / (float)N_);
    }
    __syncthreads();

    float a1 = r1b[t];
#pragma unroll 8
    for (int k = 0; k < 128; k++) a1 = fmaf(gs[k], r1w[k * 256 + t], a1);
    ts[t] = fmaxf(a1, 0.f);
    __syncthreads();

    float a2 = r2b[t];
#pragma unroll 8
    for (int k = 0; k < 256; k++) a2 = fmaf(ts[k], r2w[k * 256 + t], a2);
    out[b * 256 + t] = fmaxf(a2, 0.f);
}

// ---------------------------------------------------------------------------
extern "C" void kernel_launch(void* const* d_in, const int* in_sizes, int n_in,
                              void* d_out, int out_size)
{
    const float* obs  = (const float*)d_in[0];
    const float* e1_w = (const float*)d_in[1];
    const float* e1_b = (const float*)d_in[2];
    const float* e2_w = (const float*)d_in[3];
    const float* e2_b = (const float*)d_in[4];
    const float* g1_w = (const float*)d_in[5];
    const float* g1_b = (const float*)d_in[6];
    const float* g2_w = (const float*)d_in[7];
    const float* g2_b = (const float*)d_in[8];
    const float* g3_w = (const float*)d_in[9];
    const float* g3_b = (const float*)d_in[10];
    const float* r1_w = (const float*)d_in[11];
    const float* r1_b = (const float*)d_in[12];
    const float* r2_w = (const float*)d_in[13];
    const float* r2_b = (const float*)d_in[14];
    float* out = (float*)d_out;

    float *bufA, *bufB, *part;
    cudaGetSymbolAddress((void**)&bufA, g_bufA);
    cudaGetSymbolAddress((void**)&bufB, g_bufB);
    cudaGetSymbolAddress((void**)&part, g_part);

    const int GB = (B_ * N_) / 128;   // 512 blocks

    // smem sizes: 512 (sc) + 16384 (Ls) + 4 * 128*(K/2+1)*4
    constexpr int SM64  = 512 + 16384 + 4 * 128 * 33 * 4;   //  84,480 B
    constexpr int SM128 = 512 + 16384 + 4 * 128 * 65 * 4;   // 150,016 B
    cudaFuncSetAttribute(gcn_mma_kernel<64,  false>, cudaFuncAttributeMaxDynamicSharedMemorySize, SM64);
    cudaFuncSetAttribute(gcn_mma_kernel<128, false>, cudaFuncAttributeMaxDynamicSharedMemorySize, SM128);
    cudaFuncSetAttribute(gcn_mma_kernel<128, true >, cudaFuncAttributeMaxDynamicSharedMemorySize, SM128);

    embed_kernel<<<GB, 256>>>(obs, e1_w, e1_b, e2_w, e2_b, bufB);
    gcn_mma_kernel<64,  false><<<GB, 256, SM64 >>>(bufB, g1_w, g1_b, bufA, nullptr);
    gcn_mma_kernel<128, false><<<GB, 256, SM128>>>(bufA, g2_w, g2_b, bufB, nullptr);
    gcn_mma_kernel<128, true ><<<GB, 256, SM128>>>(bufB, g3_w, g3_b, nullptr, part);
    readout_kernel<<<B_, 256>>>(part, r1_w, r1_b, r2_w, r2_b, out);
}

// round 8
// speedup vs baseline: 1.6361x; 1.6361x over previous
#include <cuda_runtime.h>
#include <cuda_bf16.h>
#include <cstdint>

// ---------------------------------------------------------------------------
// GNNRepresentationNetwork  B=16, C=16, N=4096 (64x64), D_E=64, D_H=128, D_R=256
// embed: FFMA2 fused MLP (fp32 exact).
// GCN: mma.sync m16n8k16 bf16, 3-pass split (D = Ah*Bh + Ah*Bl + Al*Bh).
//   - weights pre-split into fragment-order global buffers (wsplit_kernel)
//   - stencil operand built into fragment-order smem (stride 66 words: even
//     -> 8B-aligned LDS.64 fragment loads; round-7 fix for misaligned address)
//   - K chunked by 64 -> ~83 KB smem -> 2 CTAs/SM
// GCN identity (exact): relu(A(hW+b)) = relu((A h)W + s_n b), s_n = deg/(deg+1e-6)
// ---------------------------------------------------------------------------

#define B_  16
#define N_  4096

typedef unsigned long long u64;

__device__ float g_bufA[B_ * 128 * N_];
__device__ float g_bufB[B_ * 128 * N_];
__device__ float g_part[B_ * 64 * 128];      // 512 blocks x 2 halves x 128 d
__device__ uint32_t g_wfh[20480];            // W frags hi: g1[0,4096) g2[4096,12288) g3[12288,20480)
__device__ uint32_t g_wfl[20480];            // W frags lo

__device__ __forceinline__ void fma2(u64& d, u64 a, u64 b) {
    asm("fma.rn.f32x2 %0, %1, %2, %0;" : "+l"(d) : "l"(a), "l"(b));
}
__device__ __forceinline__ u64 pack2(float lo, float hi) {
    u64 r; asm("mov.b64 %0, {%1, %2};" : "=l"(r) : "f"(lo), "f"(hi)); return r;
}
__device__ __forceinline__ float2 unpack2(u64 v) {
    float2 f; asm("mov.b64 {%0, %1}, %2;" : "=f"(f.x), "=f"(f.y) : "l"(v)); return f;
}
__device__ __forceinline__ float recip_deg(int deg) {
    return deg == 4 ? 0.2499999375f : (deg == 3 ? 0.3333332222f : 0.4999997500f);
}
__device__ __forceinline__ uint32_t pack_bf16(__nv_bfloat16 a, __nv_bfloat16 b) {
    return (uint32_t)__bfloat16_as_ushort(a) | ((uint32_t)__bfloat16_as_ushort(b) << 16);
}
__device__ __forceinline__ void mma_bf16(float* c, const uint32_t* a, uint32_t b0, uint32_t b1) {
    asm volatile(
        "mma.sync.aligned.m16n8k16.row.col.f32.bf16.bf16.f32 "
        "{%0,%1,%2,%3}, {%4,%5,%6,%7}, {%8,%9}, {%0,%1,%2,%3};"
        : "+f"(c[0]), "+f"(c[1]), "+f"(c[2]), "+f"(c[3])
        : "r"(a[0]), "r"(a[1]), "r"(a[2]), "r"(a[3]), "r"(b0), "r"(b1));
}

// ---------------------------------------------------------------------------
// Pre-kernel: split the 3 GCN weight matrices into bf16 hi/lo A-fragment order.
// Word layout per 64-K chunk (4096 words): [wq(4)][t(2)][ks(4)][lane(32)][j(4)]
//   j=0: d=base+grp, k=ks*16+tig*2 ; j=1: d+8 ; j=2: k+8 ; j=3: d+8,k+8
// ---------------------------------------------------------------------------
__global__ void __launch_bounds__(256)
wsplit_kernel(const float* __restrict__ g1w, const float* __restrict__ g2w,
              const float* __restrict__ g3w, uint32_t* __restrict__ wfh,
              uint32_t* __restrict__ wfl)
{
    const int idx = blockIdx.x * 256 + threadIdx.x;     // 0..20479
    const float* W; int base;
    if (idx < 4096)       { W = g1w; base = 0; }
    else if (idx < 12288) { W = g2w; base = 4096; }
    else                  { W = g3w; base = 12288; }
    const int r = idx - base;
    const int chunk = r >> 12;
    const int w = r & 4095;
    const int lane4 = w & 127, ksI = (w >> 7) & 3, t = (w >> 9) & 1, wq = (w >> 10) & 3;
    const int lane = lane4 >> 2, j = lane4 & 3;
    const int grp = lane >> 2, tig = lane & 3;
    const int d = wq * 32 + t * 16 + grp + (j & 1) * 8;
    const int kg = chunk * 64 + ksI * 16 + tig * 2 + (j >> 1) * 8;
    const float w0 = W[kg * 128 + d];
    const float w1 = W[(kg + 1) * 128 + d];
    const __nv_bfloat16 h0 = __float2bfloat16(w0);
    const __nv_bfloat16 l0 = __float2bfloat16(w0 - __bfloat162float(h0));
    const __nv_bfloat16 h1 = __float2bfloat16(w1);
    const __nv_bfloat16 l1 = __float2bfloat16(w1 - __bfloat162float(h1));
    wfh[idx] = pack_bf16(h0, h1);
    wfl[idx] = pack_bf16(l0, l1);
}

// ---------------------------------------------------------------------------
// GCN layer. Per CTA: D(128d x 128n). 8 warps: wq=wid&3 -> 32 d, nh=wid>>2 -> 64 n.
// smem: scp[128]f32 | Ls 16x256 f32 | Ah[4096] Al[4096] (u32) | Sh[4224] Sl[4224]
//   S frag word offset: (c*4+ks)*66 + lane*2 + {0,1}   (66 even -> LDS.64 aligned)
// ---------------------------------------------------------------------------
#define SMEM_GCN 83456

template <int K, bool MEAN>
__global__ void __launch_bounds__(256, 2)
gcn_mma_kernel(const float* __restrict__ in,
               const uint32_t* __restrict__ wfh, const uint32_t* __restrict__ wfl,
               const float* __restrict__ bias, float* __restrict__ out,
               float* __restrict__ part)
{
    extern __shared__ __align__(16) char smem[];
    float*    scp = reinterpret_cast<float*>(smem);
    float*    Ls  = reinterpret_cast<float*>(smem + 512);
    uint32_t* Ah  = reinterpret_cast<uint32_t*>(smem + 16896);
    uint32_t* Al  = Ah + 4096;
    uint32_t* Sh  = Al + 4096;
    uint32_t* Sl  = Sh + 4224;

    const int tid = threadIdx.x;
    const int wid = tid >> 5, lane = tid & 31;
    const int grp = lane >> 2, tig = lane & 3;
    const int wq = wid & 3, nh = wid >> 2;
    const int m0 = blockIdx.x * 128;
    const int b  = m0 >> 12, n0 = m0 & (N_ - 1);
    const float* inb = in + (size_t)b * K * N_;

    if (tid < 128) {
        const int nn = n0 + tid;
        const int gi = nn >> 6, gj = nn & 63;
        const float fd = (float)((gi > 0) + (gi < 63) + (gj > 0) + (gj < 63));
        scp[tid] = fd / (fd + 1e-6f);
    }

    // stencil-build constants (thread handles n = tid&127, k-half = tid>>7)
    const int sn  = tid & 127;
    const int kh  = tid >> 7;
    const int gn  = n0 + sn, gj2 = gn & 63;
    const bool lv = gj2 != 0, rv = gj2 != 63;
    const int dm  = ((gn >= 64) ? 1 : 0) + ((gn < N_ - 64) ? 1 : 0);
    const float rd = recip_deg(dm + (lv ? 1 : 0) + (rv ? 1 : 0));
    const int sc8 = sn >> 3, sg8 = sn & 7;

    float acc[2][8][4];
#pragma unroll
    for (int t = 0; t < 2; t++)
#pragma unroll
        for (int c = 0; c < 8; c++)
#pragma unroll
            for (int j = 0; j < 4; j++) acc[t][c][j] = 0.f;

    for (int chunk = 0; chunk < K / 64; chunk++) {
        __syncthreads();    // protect frag regions from previous chunk's readers

        // --- load pre-split W fragments (coalesced) ---
#pragma unroll
        for (int i = 0; i < 4; i++) {
            const int o = chunk * 4096 + i * 1024 + tid * 4;
            *reinterpret_cast<uint4*>(&Ah[i * 1024 + tid * 4]) =
                *reinterpret_cast<const uint4*>(&wfh[o]);
            *reinterpret_cast<uint4*>(&Al[i * 1024 + tid * 4]) =
                *reinterpret_cast<const uint4*>(&wfl[o]);
        }

        // --- build S fragments: 4 windows of 16 k ---
        for (int kw = 0; kw < 4; kw++) {
            __syncthreads();
#pragma unroll
            for (int i = 0; i < 4; i++) {
                const int idx = i * 256 + tid;
                const int r = idx >> 6, c4 = idx & 63;
                const int nw = n0 - 64 + c4 * 4;
                float4 v = make_float4(0.f, 0.f, 0.f, 0.f);
                if (nw >= 0 && nw < N_)
                    v = *reinterpret_cast<const float4*>(
                            inb + (size_t)(chunk * 64 + kw * 16 + r) * N_ + nw);
                *reinterpret_cast<float4*>(&Ls[r * 256 + c4 * 4]) = v;
            }
            __syncthreads();

            uint32_t* shp = &Sh[(sc8 * 4 + kw) * 66 + sg8 * 8 + kh];
            uint32_t* slp = &Sl[(sc8 * 4 + kw) * 66 + sg8 * 8 + kh];
#pragma unroll
            for (int p = 0; p < 4; p++) {
                __nv_bfloat16 h2[2], l2[2];
#pragma unroll
                for (int e = 0; e < 2; e++) {
                    const float* L = &Ls[(kh * 8 + p * 2 + e) * 256];
                    const float o = (L[sn] + L[sn + 128]
                                     + (lv ? L[sn + 63] : 0.f)
                                     + (rv ? L[sn + 65] : 0.f)) * rd;
                    h2[e] = __float2bfloat16(o);
                    l2[e] = __float2bfloat16(o - __bfloat162float(h2[e]));
                }
                shp[p * 2] = pack_bf16(h2[0], h2[1]);
                slp[p * 2] = pack_bf16(l2[0], l2[1]);
            }
        }
        __syncthreads();

        // --- MMA mainloop ---
#pragma unroll
        for (int ks = 0; ks < 4; ks++) {
            uint32_t ah[2][4], al[2][4];
#pragma unroll
            for (int t = 0; t < 2; t++) {
                *reinterpret_cast<uint4*>(ah[t]) =
                    *reinterpret_cast<const uint4*>(&Ah[((wq * 2 + t) * 4 + ks) * 128 + lane * 4]);
                *reinterpret_cast<uint4*>(al[t]) =
                    *reinterpret_cast<const uint4*>(&Al[((wq * 2 + t) * 4 + ks) * 128 + lane * 4]);
            }
#pragma unroll
            for (int c = 0; c < 8; c++) {
                const int cg = nh * 8 + c;
                const uint2 bh = *reinterpret_cast<const uint2*>(&Sh[(cg * 4 + ks) * 66 + lane * 2]);
                const uint2 bl = *reinterpret_cast<const uint2*>(&Sl[(cg * 4 + ks) * 66 + lane * 2]);
                mma_bf16(acc[0][c], ah[0], bh.x, bh.y);
                mma_bf16(acc[0][c], ah[0], bl.x, bl.y);
                mma_bf16(acc[0][c], al[0], bh.x, bh.y);
                mma_bf16(acc[1][c], ah[1], bh.x, bh.y);
                mma_bf16(acc[1][c], ah[1], bl.x, bl.y);
                mma_bf16(acc[1][c], al[1], bh.x, bh.y);
            }
        }
    }

    // --- Epilogue: scaled bias + relu ---
    const int d0 = wq * 32 + grp;
    const float bv[4] = { __ldg(&bias[d0]),      __ldg(&bias[d0 + 8]),
                          __ldg(&bias[d0 + 16]), __ldg(&bias[d0 + 24]) };

    if (!MEAN) {
        float* ob = out + (size_t)b * 128 * N_ + n0;
#pragma unroll
        for (int t = 0; t < 2; t++) {
            float* r0 = ob + (size_t)(d0 + t * 16) * N_;
            float* r1 = r0 + (size_t)8 * N_;
#pragma unroll
            for (int c = 0; c < 8; c++) {
                const int nn = nh * 64 + c * 8 + tig * 2;
                const float s0 = scp[nn], s1 = scp[nn + 1];
                float2 v0, v1;
                v0.x = fmaxf(fmaf(s0, bv[t * 2], acc[t][c][0]), 0.f);
                v0.y = fmaxf(fmaf(s1, bv[t * 2], acc[t][c][1]), 0.f);
                v1.x = fmaxf(fmaf(s0, bv[t * 2 + 1], acc[t][c][2]), 0.f);
                v1.y = fmaxf(fmaf(s1, bv[t * 2 + 1], acc[t][c][3]), 0.f);
                *reinterpret_cast<float2*>(r0 + nn) = v0;
                *reinterpret_cast<float2*>(r1 + nn) = v1;
            }
        }
    } else {
        float sums[4] = { 0.f, 0.f, 0.f, 0.f };
#pragma unroll
        for (int t = 0; t < 2; t++)
#pragma unroll
            for (int c = 0; c < 8; c++) {
                const int nn = nh * 64 + c * 8 + tig * 2;
                const float s0 = scp[nn], s1 = scp[nn + 1];
                sums[t * 2]     += fmaxf(fmaf(s0, bv[t * 2], acc[t][c][0]), 0.f)
                                 + fmaxf(fmaf(s1, bv[t * 2], acc[t][c][1]), 0.f);
                sums[t * 2 + 1] += fmaxf(fmaf(s0, bv[t * 2 + 1], acc[t][c][2]), 0.f)
                                 + fmaxf(fmaf(s1, bv[t * 2 + 1], acc[t][c][3]), 0.f);
            }
#pragma unroll
        for (int q = 0; q < 4; q++) {
            sums[q] += __shfl_xor_sync(0xffffffffu, sums[q], 1);
            sums[q] += __shfl_xor_sync(0xffffffffu, sums[q], 2);
        }
        if (tig == 0) {
            float* pp = part + ((size_t)blockIdx.x * 2 + nh) * 128;
            pp[d0]      = sums[0];
            pp[d0 + 8]  = sums[1];
            pp[d0 + 16] = sums[2];
            pp[d0 + 24] = sums[3];
        }
    }
}

// ---------------------------------------------------------------------------
// Fused embed MLP (FFMA2): out = relu(relu(x W1 + b1) W2 + b2)
// ---------------------------------------------------------------------------
__global__ void __launch_bounds__(256)
embed_kernel(const float* __restrict__ obs,
             const float* __restrict__ w1, const float* __restrict__ b1,
             const float* __restrict__ w2, const float* __restrict__ b2,
             float* __restrict__ out)
{
    __shared__ __align__(16) float Xs[16 * 128];
    __shared__ __align__(16) float Ws[16 * 64];
    __shared__ __align__(16) float Hs[64 * 128];

    const int tid = threadIdx.x, tx = tid & 15, ty = tid >> 4;
    const int m0 = blockIdx.x * 128;
    const int b  = m0 >> 12, n0 = m0 & (N_ - 1);
    const float* xb = obs + (size_t)b * 16 * N_ + n0;

    {
        const int i0 = tid, i1 = tid + 256;
        *reinterpret_cast<float4*>(&Xs[(i0 >> 5) * 128 + (i0 & 31) * 4]) =
            *(reinterpret_cast<const float4*>(xb + (size_t)(i0 >> 5) * N_) + (i0 & 31));
        *reinterpret_cast<float4*>(&Xs[(i1 >> 5) * 128 + (i1 & 31) * 4]) =
            *(reinterpret_cast<const float4*>(xb + (size_t)(i1 >> 5) * N_) + (i1 & 31));
    }
    *reinterpret_cast<float4*>(&Ws[tid * 4]) = *(reinterpret_cast<const float4*>(w1) + tid);
    __syncthreads();

    u64 acc[4][4];
#pragma unroll
    for (int dd = 0; dd < 4; dd++) {
        const float bv = b1[ty * 4 + dd];
        const u64 bp = pack2(bv, bv);
#pragma unroll
        for (int j = 0; j < 4; j++) acc[dd][j] = bp;
    }
#pragma unroll
    for (int k = 0; k < 16; k++) {
        const ulonglong2 a01 = *reinterpret_cast<const ulonglong2*>(&Xs[k * 128 + tx * 8]);
        const ulonglong2 a23 = *reinterpret_cast<const ulonglong2*>(&Xs[k * 128 + tx * 8 + 4]);
        const u64 a[4] = { a01.x, a01.y, a23.x, a23.y };
        const float4 w = *reinterpret_cast<const float4*>(&Ws[k * 64 + ty * 4]);
        const float wv[4] = { w.x, w.y, w.z, w.w };
#pragma unroll
        for (int dd = 0; dd < 4; dd++) {
            const u64 wd = pack2(wv[dd], wv[dd]);
#pragma unroll
            for (int j = 0; j < 4; j++) fma2(acc[dd][j], wd, a[j]);
        }
    }
#pragma unroll
    for (int dd = 0; dd < 4; dd++) {
        float* hr = &Hs[(ty * 4 + dd) * 128 + tx * 8];
#pragma unroll
        for (int j = 0; j < 4; j += 2) {
            const float2 p0 = unpack2(acc[dd][j]), p1 = unpack2(acc[dd][j + 1]);
            float4 o = { fmaxf(p0.x, 0.f), fmaxf(p0.y, 0.f), fmaxf(p1.x, 0.f), fmaxf(p1.y, 0.f) };
            *reinterpret_cast<float4*>(hr + j * 2) = o;
        }
    }
    __syncthreads();

    u64 acc2[4][4];
#pragma unroll
    for (int dd = 0; dd < 4; dd++) {
        const float bv = b2[ty * 4 + dd];
        const u64 bp = pack2(bv, bv);
#pragma unroll
        for (int j = 0; j < 4; j++) acc2[dd][j] = bp;
    }
    for (int kc = 0; kc < 64; kc += 16) {
        __syncthreads();
        *reinterpret_cast<float4*>(&Ws[tid * 4]) =
            *(reinterpret_cast<const float4*>(w2 + kc * 64) + tid);
        __syncthreads();
#pragma unroll
        for (int k = 0; k < 16; k++) {
            const ulonglong2 a01 = *reinterpret_cast<const ulonglong2*>(&Hs[(kc + k) * 128 + tx * 8]);
            const ulonglong2 a23 = *reinterpret_cast<const ulonglong2*>(&Hs[(kc + k) * 128 + tx * 8 + 4]);
            const u64 a[4] = { a01.x, a01.y, a23.x, a23.y };
            const float4 w = *reinterpret_cast<const float4*>(&Ws[k * 64 + ty * 4]);
            const float wv[4] = { w.x, w.y, w.z, w.w };
#pragma unroll
            for (int dd = 0; dd < 4; dd++) {
                const u64 wd = pack2(wv[dd], wv[dd]);
#pragma unroll
                for (int j = 0; j < 4; j++) fma2(acc2[dd][j], wd, a[j]);
            }
        }
    }

    float* ob = out + (size_t)b * 64 * N_ + n0 + tx * 8;
#pragma unroll
    for (int dd = 0; dd < 4; dd++) {
        float* orow = ob + (size_t)(ty * 4 + dd) * N_;
#pragma unroll
        for (int j = 0; j < 4; j += 2) {
            const float2 p0 = unpack2(acc2[dd][j]), p1 = unpack2(acc2[dd][j + 1]);
            float4 o = { fmaxf(p0.x, 0.f), fmaxf(p0.y, 0.f), fmaxf(p1.x, 0.f), fmaxf(p1.y, 0.f) };
            *reinterpret_cast<float4*>(orow + j * 2) = o;
        }
    }
}

// ---------------------------------------------------------------------------
// Readout: g[b] = mean of 64 partials; out = relu(relu(g r1 + b1) r2 + b2)
// ---------------------------------------------------------------------------
__global__ void __launch_bounds__(256)
readout_kernel(const float* __restrict__ part,
               const float* __restrict__ r1w, const float* __restrict__ r1b,
               const float* __restrict__ r2w, const float* __restrict__ r2b,
               float* __restrict__ out)
{
    __shared__ float gs[128];
    __shared__ float ts[256];
    const int b = blockIdx.x, t = threadIdx.x;

    if (t < 128) {
        float s = 0.f;
        const float* p = part + (size_t)b * 64 * 128 + t;
#pragma unroll
        for (int k = 0; k < 64; k++) s += p[k * 128];
        gs[t] = s * (1.0f / (float)N_);
    }
    __syncthreads();

    float a1 = r1b[t];
#pragma unroll 8
    for (int k = 0; k < 128; k++) a1 = fmaf(gs[k], r1w[k * 256 + t], a1);
    ts[t] = fmaxf(a1, 0.f);
    __syncthreads();

    float a2 = r2b[t];
#pragma unroll 8
    for (int k = 0; k < 256; k++) a2 = fmaf(ts[k], r2w[k * 256 + t], a2);
    out[b * 256 + t] = fmaxf(a2, 0.f);
}

// ---------------------------------------------------------------------------
extern "C" void kernel_launch(void* const* d_in, const int* in_sizes, int n_in,
                              void* d_out, int out_size)
{
    const float* obs  = (const float*)d_in[0];
    const float* e1_w = (const float*)d_in[1];
    const float* e1_b = (const float*)d_in[2];
    const float* e2_w = (const float*)d_in[3];
    const float* e2_b = (const float*)d_in[4];
    const float* g1_w = (const float*)d_in[5];
    const float* g1_b = (const float*)d_in[6];
    const float* g2_w = (const float*)d_in[7];
    const float* g2_b = (const float*)d_in[8];
    const float* g3_w = (const float*)d_in[9];
    const float* g3_b = (const float*)d_in[10];
    const float* r1_w = (const float*)d_in[11];
    const float* r1_b = (const float*)d_in[12];
    const float* r2_w = (const float*)d_in[13];
    const float* r2_b = (const float*)d_in[14];
    float* out = (float*)d_out;

    float *bufA, *bufB, *part;
    uint32_t *wfh, *wfl;
    cudaGetSymbolAddress((void**)&bufA, g_bufA);
    cudaGetSymbolAddress((void**)&bufB, g_bufB);
    cudaGetSymbolAddress((void**)&part, g_part);
    cudaGetSymbolAddress((void**)&wfh,  g_wfh);
    cudaGetSymbolAddress((void**)&wfl,  g_wfl);

    const int GB = (B_ * N_) / 128;   // 512 blocks

    cudaFuncSetAttribute(gcn_mma_kernel<64,  false>, cudaFuncAttributeMaxDynamicSharedMemorySize, SMEM_GCN);
    cudaFuncSetAttribute(gcn_mma_kernel<128, false>, cudaFuncAttributeMaxDynamicSharedMemorySize, SMEM_GCN);
    cudaFuncSetAttribute(gcn_mma_kernel<128, true >, cudaFuncAttributeMaxDynamicSharedMemorySize, SMEM_GCN);

    wsplit_kernel<<<80, 256>>>(g1_w, g2_w, g3_w, wfh, wfl);
    embed_kernel<<<GB, 256>>>(obs, e1_w, e1_b, e2_w, e2_b, bufB);
    gcn_mma_kernel<64,  false><<<GB, 256, SMEM_GCN>>>(bufB, wfh,         wfl,         g1_b, bufA, nullptr);
    gcn_mma_kernel<128, false><<<GB, 256, SMEM_GCN>>>(bufA, wfh + 4096,  wfl + 4096,  g2_b, bufB, nullptr);
    gcn_mma_kernel<128, true ><<<GB, 256, SMEM_GCN>>>(bufB, wfh + 12288, wfl + 12288, g3_b, nullptr, part);
    readout_kernel<<<B_, 256>>>(part, r1_w, r1_b, r2_w, r2_b, out);
}

// round 9
// speedup vs baseline: 1.9380x; 1.1846x over previous
#include <cuda_runtime.h>
#include <cuda_bf16.h>
#include <cstdint>

// ---------------------------------------------------------------------------
// GNNRepresentationNetwork  B=16, C=16, N=4096 (64x64), D_E=64, D_H=128, D_R=256
// embed: FFMA2 fused MLP (fp32 exact).
// GCN: mma.sync m16n8k16 bf16, 3-pass split (D = Ah*Bh + Ah*Bl + Al*Bh).
//   - weights pre-split into fragment-order global buffers (wsplit_kernel)
//   - cp.async pipelined staging: double-buffered halo windows + W frags
//   - vectorized stencil build (2k x 4n per thread, float4 loads)
//   - K chunked by 64 -> ~100 KB smem -> 2 CTAs/SM
// GCN identity (exact): relu(A(hW+b)) = relu((A h)W + s_n b), s_n = deg/(deg+1e-6)
// ---------------------------------------------------------------------------

#define B_  16
#define N_  4096

typedef unsigned long long u64;

__device__ float g_bufA[B_ * 128 * N_];
__device__ float g_bufB[B_ * 128 * N_];
__device__ float g_part[B_ * 64 * 128];      // 512 blocks x 2 halves x 128 d
__device__ uint32_t g_wfh[20480];            // W frags hi: g1[0,4096) g2[4096,12288) g3[12288,20480)
__device__ uint32_t g_wfl[20480];            // W frags lo

__device__ __forceinline__ void fma2(u64& d, u64 a, u64 b) {
    asm("fma.rn.f32x2 %0, %1, %2, %0;" : "+l"(d) : "l"(a), "l"(b));
}
__device__ __forceinline__ u64 pack2(float lo, float hi) {
    u64 r; asm("mov.b64 %0, {%1, %2};" : "=l"(r) : "f"(lo), "f"(hi)); return r;
}
__device__ __forceinline__ float2 unpack2(u64 v) {
    float2 f; asm("mov.b64 {%0, %1}, %2;" : "=f"(f.x), "=f"(f.y) : "l"(v)); return f;
}
__device__ __forceinline__ float recip_deg(int deg) {
    return deg == 4 ? 0.2499999375f : (deg == 3 ? 0.3333332222f : 0.4999997500f);
}
__device__ __forceinline__ uint32_t pack_bf16(__nv_bfloat16 a, __nv_bfloat16 b) {
    return (uint32_t)__bfloat16_as_ushort(a) | ((uint32_t)__bfloat16_as_ushort(b) << 16);
}
__device__ __forceinline__ void mma_bf16(float* c, const uint32_t* a, uint32_t b0, uint32_t b1) {
    asm volatile(
        "mma.sync.aligned.m16n8k16.row.col.f32.bf16.bf16.f32 "
        "{%0,%1,%2,%3}, {%4,%5,%6,%7}, {%8,%9}, {%0,%1,%2,%3};"
        : "+f"(c[0]), "+f"(c[1]), "+f"(c[2]), "+f"(c[3])
        : "r"(a[0]), "r"(a[1]), "r"(a[2]), "r"(a[3]), "r"(b0), "r"(b1));
}
__device__ __forceinline__ void cp16(uint32_t daddr, const void* g, int sz) {
    asm volatile("cp.async.cg.shared.global [%0], [%1], 16, %2;"
                 :: "r"(daddr), "l"(g), "r"(sz) : "memory");
}
#define CP_COMMIT() asm volatile("cp.async.commit_group;" ::: "memory")
#define CP_WAIT0()  asm volatile("cp.async.wait_group 0;" ::: "memory")

// ---------------------------------------------------------------------------
// Pre-kernel: split the 3 GCN weight matrices into bf16 hi/lo A-fragment order.
// Word layout per 64-K chunk (4096 words): [wq(4)][t(2)][ks(4)][lane(32)][j(4)]
// ---------------------------------------------------------------------------
__global__ void __launch_bounds__(256)
wsplit_kernel(const float* __restrict__ g1w, const float* __restrict__ g2w,
              const float* __restrict__ g3w, uint32_t* __restrict__ wfh,
              uint32_t* __restrict__ wfl)
{
    const int idx = blockIdx.x * 256 + threadIdx.x;     // 0..20479
    const float* W; int base;
    if (idx < 4096)       { W = g1w; base = 0; }
    else if (idx < 12288) { W = g2w; base = 4096; }
    else                  { W = g3w; base = 12288; }
    const int r = idx - base;
    const int chunk = r >> 12;
    const int w = r & 4095;
    const int lane4 = w & 127, ksI = (w >> 7) & 3, t = (w >> 9) & 1, wq = (w >> 10) & 3;
    const int lane = lane4 >> 2, j = lane4 & 3;
    const int grp = lane >> 2, tig = lane & 3;
    const int d = wq * 32 + t * 16 + grp + (j & 1) * 8;
    const int kg = chunk * 64 + ksI * 16 + tig * 2 + (j >> 1) * 8;
    const float w0 = W[kg * 128 + d];
    const float w1 = W[(kg + 1) * 128 + d];
    const __nv_bfloat16 h0 = __float2bfloat16(w0);
    const __nv_bfloat16 l0 = __float2bfloat16(w0 - __bfloat162float(h0));
    const __nv_bfloat16 h1 = __float2bfloat16(w1);
    const __nv_bfloat16 l1 = __float2bfloat16(w1 - __bfloat162float(h1));
    wfh[idx] = pack_bf16(h0, h1);
    wfl[idx] = pack_bf16(l0, l1);
}

// ---------------------------------------------------------------------------
// GCN layer. Per CTA: D(128d x 128n). 8 warps: wq=wid&3 -> 32 d, nh=wid>>2 -> 64 n.
// smem bytes: scp[0,512) | Ls 2x16x256 f32 [512,33280) | Ah[33280,49664)
//             Al[49664,66048) | Sh[66048,82944) | Sl[82944,99840)
//   S frag word offset: (c*4+kw)*66 + (n&7)*8 + idx, idx = kb<8 ? kb : kb-7
// ---------------------------------------------------------------------------
#define SMEM_GCN 99840

__device__ __forceinline__ void issue_window(uint32_t LsBufA, const float* inb,
                                             int kbase, int n0, int tid)
{
#pragma unroll
    for (int i = 0; i < 4; i++) {
        const int idx = i * 256 + tid;
        const int r = idx >> 6, c4 = idx & 63;
        const int nw = n0 - 64 + c4 * 4;
        const bool v = (nw >= 0) && (nw < N_);
        const float* g = v ? (inb + (size_t)(kbase + r) * N_ + nw) : inb;
        cp16(LsBufA + (uint32_t)((r * 256 + c4 * 4) * 4), g, v ? 16 : 0);
    }
}

template <int K, bool MEAN>
__global__ void __launch_bounds__(256, 2)
gcn_mma_kernel(const float* __restrict__ in,
               const uint32_t* __restrict__ wfh, const uint32_t* __restrict__ wfl,
               const float* __restrict__ bias, float* __restrict__ out,
               float* __restrict__ part)
{
    extern __shared__ __align__(16) char smem[];
    float*    scp = reinterpret_cast<float*>(smem);
    float*    Ls  = reinterpret_cast<float*>(smem + 512);
    uint32_t* Ah  = reinterpret_cast<uint32_t*>(smem + 33280);
    uint32_t* Al  = Ah + 4096;
    uint32_t* Sh  = Al + 4096;
    uint32_t* Sl  = Sh + 4224;

    uint32_t sb;
    asm("{ .reg .u64 t; cvta.to.shared.u64 t, %1; cvt.u32.u64 %0, t; }" : "=r"(sb) : "l"(smem));
    const uint32_t LsA = sb + 512;
    const uint32_t AhA = sb + 33280;
    const uint32_t AlA = AhA + 16384;

    const int tid = threadIdx.x;
    const int wid = tid >> 5, lane = tid & 31;
    const int grp = lane >> 2, tig = lane & 3;
    const int wq = wid & 3, nh = wid >> 2;
    const int m0 = blockIdx.x * 128;
    const int b  = m0 >> 12, n0 = m0 & (N_ - 1);
    const float* inb = in + (size_t)b * K * N_;

    if (tid < 128) {
        const int nn = n0 + tid;
        const int gi = nn >> 6, gj = nn & 63;
        const float fd = (float)((gi > 0) + (gi < 63) + (gj > 0) + (gj < 63));
        scp[tid] = fd / (fd + 1e-6f);
    }

    // S-build constants: thread handles k-pair kp (2 k) x 4 n starting at n4
    const int kp = tid >> 5;
    const int n4 = (tid & 31) * 4;
    const int gi2 = (n0 + n4) >> 6;
    const int dm  = (gi2 > 0) + (gi2 < 63);
    const bool lv0 = (n4 & 63) != 0;           // n0 % 128 == 0
    const bool rv3 = ((n4 + 3) & 63) != 63;
    const float rd0  = recip_deg(dm + (lv0 ? 1 : 0) + 1);
    const float rd12 = recip_deg(dm + 2);
    const float rd3  = recip_deg(dm + 1 + (rv3 ? 1 : 0));
    const int kb  = kp * 2;
    const int sidx = kb < 8 ? kb : kb - 7;
    const int rowc = (n4 >> 3) * 4;            // c-row base
    const int rowo = sidx + (n4 & 7) * 8;      // within-row word base

    float acc[2][8][4];
#pragma unroll
    for (int t = 0; t < 2; t++)
#pragma unroll
        for (int c = 0; c < 8; c++)
#pragma unroll
            for (int j = 0; j < 4; j++) acc[t][c][j] = 0.f;

    // Prologue: W chunk 0 + halo window 0
#pragma unroll
    for (int i = 0; i < 4; i++) {
        cp16(AhA + (uint32_t)((i * 1024 + tid * 4) * 4), &wfh[i * 1024 + tid * 4], 16);
        cp16(AlA + (uint32_t)((i * 1024 + tid * 4) * 4), &wfl[i * 1024 + tid * 4], 16);
    }
    issue_window(LsA, inb, 0, n0, tid);
    CP_COMMIT();

    constexpr int NCH = K / 64;
    for (int chunk = 0; chunk < NCH; chunk++) {
        for (int kw = 0; kw < 4; kw++) {
            CP_WAIT0();
            __syncthreads();

            const int wg = chunk * 4 + kw;
            // issue next window (other buffer) + next chunk's W frags at kw==0
            if (wg + 1 < NCH * 4) {
                const int nwg = wg + 1;
                issue_window(LsA + (uint32_t)((nwg & 1) * 16384), inb,
                             (nwg >> 2) * 64 + (nwg & 3) * 16, n0, tid);
            }
            if (kw == 0 && chunk > 0) {
#pragma unroll
                for (int i = 0; i < 4; i++) {
                    cp16(AhA + (uint32_t)((i * 1024 + tid * 4) * 4),
                         &wfh[chunk * 4096 + i * 1024 + tid * 4], 16);
                    cp16(AlA + (uint32_t)((i * 1024 + tid * 4) * 4),
                         &wfl[chunk * 4096 + i * 1024 + tid * 4], 16);
                }
            }
            CP_COMMIT();

            // Build S(kw) from current buffer: 2 k x 4 n per thread
            const float* Lb = Ls + (wg & 1) * 4096;
            float o[2][4];
#pragma unroll
            for (int e = 0; e < 2; e++) {
                const float* L = Lb + (kp * 2 + e) * 256 + n4;
                const float4 up = *reinterpret_cast<const float4*>(L);
                const float4 ct = *reinterpret_cast<const float4*>(L + 64);
                const float4 dn = *reinterpret_cast<const float4*>(L + 128);
                const float lf = lv0 ? L[63] : 0.f;
                const float rt = rv3 ? L[68] : 0.f;
                o[e][0] = (up.x + dn.x + lf   + ct.y) * rd0;
                o[e][1] = (up.y + dn.y + ct.x + ct.z) * rd12;
                o[e][2] = (up.z + dn.z + ct.y + ct.w) * rd12;
                o[e][3] = (up.w + dn.w + ct.z + rt  ) * rd3;
            }
            const int wbase = (rowc + kw) * 66 + rowo;
#pragma unroll
            for (int i = 0; i < 4; i++) {
                const __nv_bfloat16 h0 = __float2bfloat16(o[0][i]);
                const __nv_bfloat16 h1 = __float2bfloat16(o[1][i]);
                const __nv_bfloat16 l0 = __float2bfloat16(o[0][i] - __bfloat162float(h0));
                const __nv_bfloat16 l1 = __float2bfloat16(o[1][i] - __bfloat162float(h1));
                Sh[wbase + i * 8] = pack_bf16(h0, h1);
                Sl[wbase + i * 8] = pack_bf16(l0, l1);
            }
        }
        __syncthreads();

        // --- MMA mainloop ---
#pragma unroll
        for (int ks = 0; ks < 4; ks++) {
            uint32_t ah[2][4], al[2][4];
#pragma unroll
            for (int t = 0; t < 2; t++) {
                *reinterpret_cast<uint4*>(ah[t]) =
                    *reinterpret_cast<const uint4*>(&Ah[((wq * 2 + t) * 4 + ks) * 128 + lane * 4]);
                *reinterpret_cast<uint4*>(al[t]) =
                    *reinterpret_cast<const uint4*>(&Al[((wq * 2 + t) * 4 + ks) * 128 + lane * 4]);
            }
#pragma unroll
            for (int c = 0; c < 8; c++) {
                const int cg = nh * 8 + c;
                const uint2 bh = *reinterpret_cast<const uint2*>(&Sh[(cg * 4 + ks) * 66 + lane * 2]);
                const uint2 bl = *reinterpret_cast<const uint2*>(&Sl[(cg * 4 + ks) * 66 + lane * 2]);
                mma_bf16(acc[0][c], ah[0], bh.x, bh.y);
                mma_bf16(acc[0][c], ah[0], bl.x, bl.y);
                mma_bf16(acc[0][c], al[0], bh.x, bh.y);
                mma_bf16(acc[1][c], ah[1], bh.x, bh.y);
                mma_bf16(acc[1][c], ah[1], bl.x, bl.y);
                mma_bf16(acc[1][c], al[1], bh.x, bh.y);
            }
        }
    }

    // --- Epilogue: scaled bias + relu ---
    const int d0 = wq * 32 + grp;
    const float bv[4] = { __ldg(&bias[d0]),      __ldg(&bias[d0 + 8]),
                          __ldg(&bias[d0 + 16]), __ldg(&bias[d0 + 24]) };

    if (!MEAN) {
        float* ob = out + (size_t)b * 128 * N_ + n0;
#pragma unroll
        for (int t = 0; t < 2; t++) {
            float* r0 = ob + (size_t)(d0 + t * 16) * N_;
            float* r1 = r0 + (size_t)8 * N_;
#pragma unroll
            for (int c = 0; c < 8; c++) {
                const int nn = nh * 64 + c * 8 + tig * 2;
                const float s0 = scp[nn], s1 = scp[nn + 1];
                float2 v0, v1;
                v0.x = fmaxf(fmaf(s0, bv[t * 2], acc[t][c][0]), 0.f);
                v0.y = fmaxf(fmaf(s1, bv[t * 2], acc[t][c][1]), 0.f);
                v1.x = fmaxf(fmaf(s0, bv[t * 2 + 1], acc[t][c][2]), 0.f);
                v1.y = fmaxf(fmaf(s1, bv[t * 2 + 1], acc[t][c][3]), 0.f);
                *reinterpret_cast<float2*>(r0 + nn) = v0;
                *reinterpret_cast<float2*>(r1 + nn) = v1;
            }
        }
    } else {
        float sums[4] = { 0.f, 0.f, 0.f, 0.f };
#pragma unroll
        for (int t = 0; t < 2; t++)
#pragma unroll
            for (int c = 0; c < 8; c++) {
                const int nn = nh * 64 + c * 8 + tig * 2;
                const float s0 = scp[nn], s1 = scp[nn + 1];
                sums[t * 2]     += fmaxf(fmaf(s0, bv[t * 2], acc[t][c][0]), 0.f)
                                 + fmaxf(fmaf(s1, bv[t * 2], acc[t][c][1]), 0.f);
                sums[t * 2 + 1] += fmaxf(fmaf(s0, bv[t * 2 + 1], acc[t][c][2]), 0.f)
                                 + fmaxf(fmaf(s1, bv[t * 2 + 1], acc[t][c][3]), 0.f);
            }
#pragma unroll
        for (int q = 0; q < 4; q++) {
            sums[q] += __shfl_xor_sync(0xffffffffu, sums[q], 1);
            sums[q] += __shfl_xor_sync(0xffffffffu, sums[q], 2);
        }
        if (tig == 0) {
            float* pp = part + ((size_t)blockIdx.x * 2 + nh) * 128;
            pp[d0]      = sums[0];
            pp[d0 + 8]  = sums[1];
            pp[d0 + 16] = sums[2];
            pp[d0 + 24] = sums[3];
        }
    }
}

// ---------------------------------------------------------------------------
// Fused embed MLP (FFMA2): out = relu(relu(x W1 + b1) W2 + b2)
// ---------------------------------------------------------------------------
__global__ void __launch_bounds__(256)
embed_kernel(const float* __restrict__ obs,
             const float* __restrict__ w1, const float* __restrict__ b1,
             const float* __restrict__ w2, const float* __restrict__ b2,
             float* __restrict__ out)
{
    __shared__ __align__(16) float Xs[16 * 128];
    __shared__ __align__(16) float Ws[16 * 64];
    __shared__ __align__(16) float Hs[64 * 128];

    const int tid = threadIdx.x, tx = tid & 15, ty = tid >> 4;
    const int m0 = blockIdx.x * 128;
    const int b  = m0 >> 12, n0 = m0 & (N_ - 1);
    const float* xb = obs + (size_t)b * 16 * N_ + n0;

    {
        const int i0 = tid, i1 = tid + 256;
        *reinterpret_cast<float4*>(&Xs[(i0 >> 5) * 128 + (i0 & 31) * 4]) =
            *(reinterpret_cast<const float4*>(xb + (size_t)(i0 >> 5) * N_) + (i0 & 31));
        *reinterpret_cast<float4*>(&Xs[(i1 >> 5) * 128 + (i1 & 31) * 4]) =
            *(reinterpret_cast<const float4*>(xb + (size_t)(i1 >> 5) * N_) + (i1 & 31));
    }
    *reinterpret_cast<float4*>(&Ws[tid * 4]) = *(reinterpret_cast<const float4*>(w1) + tid);
    __syncthreads();

    u64 acc[4][4];
#pragma unroll
    for (int dd = 0; dd < 4; dd++) {
        const float bv = b1[ty * 4 + dd];
        const u64 bp = pack2(bv, bv);
#pragma unroll
        for (int j = 0; j < 4; j++) acc[dd][j] = bp;
    }
#pragma unroll
    for (int k = 0; k < 16; k++) {
        const ulonglong2 a01 = *reinterpret_cast<const ulonglong2*>(&Xs[k * 128 + tx * 8]);
        const ulonglong2 a23 = *reinterpret_cast<const ulonglong2*>(&Xs[k * 128 + tx * 8 + 4]);
        const u64 a[4] = { a01.x, a01.y, a23.x, a23.y };
        const float4 w = *reinterpret_cast<const float4*>(&Ws[k * 64 + ty * 4]);
        const float wv[4] = { w.x, w.y, w.z, w.w };
#pragma unroll
        for (int dd = 0; dd < 4; dd++) {
            const u64 wd = pack2(wv[dd], wv[dd]);
#pragma unroll
            for (int j = 0; j < 4; j++) fma2(acc[dd][j], wd, a[j]);
        }
    }
#pragma unroll
    for (int dd = 0; dd < 4; dd++) {
        float* hr = &Hs[(ty * 4 + dd) * 128 + tx * 8];
#pragma unroll
        for (int j = 0; j < 4; j += 2) {
            const float2 p0 = unpack2(acc[dd][j]), p1 = unpack2(acc[dd][j + 1]);
            float4 o = { fmaxf(p0.x, 0.f), fmaxf(p0.y, 0.f), fmaxf(p1.x, 0.f), fmaxf(p1.y, 0.f) };
            *reinterpret_cast<float4*>(hr + j * 2) = o;
        }
    }
    __syncthreads();

    u64 acc2[4][4];
#pragma unroll
    for (int dd = 0; dd < 4; dd++) {
        const float bv = b2[ty * 4 + dd];
        const u64 bp = pack2(bv, bv);
#pragma unroll
        for (int j = 0; j < 4; j++) acc2[dd][j] = bp;
    }
    for (int kc = 0; kc < 64; kc += 16) {
        __syncthreads();
        *reinterpret_cast<float4*>(&Ws[tid * 4]) =
            *(reinterpret_cast<const float4*>(w2 + kc * 64) + tid);
        __syncthreads();
#pragma unroll
        for (int k = 0; k < 16; k++) {
            const ulonglong2 a01 = *reinterpret_cast<const ulonglong2*>(&Hs[(kc + k) * 128 + tx * 8]);
            const ulonglong2 a23 = *reinterpret_cast<const ulonglong2*>(&Hs[(kc + k) * 128 + tx * 8 + 4]);
            const u64 a[4] = { a01.x, a01.y, a23.x, a23.y };
            const float4 w = *reinterpret_cast<const float4*>(&Ws[k * 64 + ty * 4]);
            const float wv[4] = { w.x, w.y, w.z, w.w };
#pragma unroll
            for (int dd = 0; dd < 4; dd++) {
                const u64 wd = pack2(wv[dd], wv[dd]);
#pragma unroll
                for (int j = 0; j < 4; j++) fma2(acc2[dd][j], wd, a[j]);
            }
        }
    }

    float* ob = out + (size_t)b * 64 * N_ + n0 + tx * 8;
#pragma unroll
    for (int dd = 0; dd < 4; dd++) {
        float* orow = ob + (size_t)(ty * 4 + dd) * N_;
#pragma unroll
        for (int j = 0; j < 4; j += 2) {
            const float2 p0 = unpack2(acc2[dd][j]), p1 = unpack2(acc2[dd][j + 1]);
            float4 o = { fmaxf(p0.x, 0.f), fmaxf(p0.y, 0.f), fmaxf(p1.x, 0.f), fmaxf(p1.y, 0.f) };
            *reinterpret_cast<float4*>(orow + j * 2) = o;
        }
    }
}

// ---------------------------------------------------------------------------
// Readout: g[b] = mean of 64 partials; out = relu(relu(g r1 + b1) r2 + b2)
// ---------------------------------------------------------------------------
__global__ void __launch_bounds__(256)
readout_kernel(const float* __restrict__ part,
               const float* __restrict__ r1w, const float* __restrict__ r1b,
               const float* __restrict__ r2w, const float* __restrict__ r2b,
               float* __restrict__ out)
{
    __shared__ float gs[128];
    __shared__ float ts[256];
    const int b = blockIdx.x, t = threadIdx.x;

    if (t < 128) {
        float s = 0.f;
        const float* p = part + (size_t)b * 64 * 128 + t;
#pragma unroll
        for (int k = 0; k < 64; k++) s += p[k * 128];
        gs[t] = s * (1.0f / (float)N_);
    }
    __syncthreads();

    float a1 = r1b[t];
#pragma unroll 8
    for (int k = 0; k < 128; k++) a1 = fmaf(gs[k], r1w[k * 256 + t], a1);
    ts[t] = fmaxf(a1, 0.f);
    __syncthreads();

    float a2 = r2b[t];
#pragma unroll 8
    for (int k = 0; k < 256; k++) a2 = fmaf(ts[k], r2w[k * 256 + t], a2);
    out[b * 256 + t] = fmaxf(a2, 0.f);
}

// ---------------------------------------------------------------------------
extern "C" void kernel_launch(void* const* d_in, const int* in_sizes, int n_in,
                              void* d_out, int out_size)
{
    const float* obs  = (const float*)d_in[0];
    const float* e1_w = (const float*)d_in[1];
    const float* e1_b = (const float*)d_in[2];
    const float* e2_w = (const float*)d_in[3];
    const float* e2_b = (const float*)d_in[4];
    const float* g1_w = (const float*)d_in[5];
    const float* g1_b = (const float*)d_in[6];
    const float* g2_w = (const float*)d_in[7];
    const float* g2_b = (const float*)d_in[8];
    const float* g3_w = (const float*)d_in[9];
    const float* g3_b = (const float*)d_in[10];
    const float* r1_w = (const float*)d_in[11];
    const float* r1_b = (const float*)d_in[12];
    const float* r2_w = (const float*)d_in[13];
    const float* r2_b = (const float*)d_in[14];
    float* out = (float*)d_out;

    float *bufA, *bufB, *part;
    uint32_t *wfh, *wfl;
    cudaGetSymbolAddress((void**)&bufA, g_bufA);
    cudaGetSymbolAddress((void**)&bufB, g_bufB);
    cudaGetSymbolAddress((void**)&part, g_part);
    cudaGetSymbolAddress((void**)&wfh,  g_wfh);
    cudaGetSymbolAddress((void**)&wfl,  g_wfl);

    const int GB = (B_ * N_) / 128;   // 512 blocks

    cudaFuncSetAttribute(gcn_mma_kernel<64,  false>, cudaFuncAttributeMaxDynamicSharedMemorySize, SMEM_GCN);
    cudaFuncSetAttribute(gcn_mma_kernel<128, false>, cudaFuncAttributeMaxDynamicSharedMemorySize, SMEM_GCN);
    cudaFuncSetAttribute(gcn_mma_kernel<128, true >, cudaFuncAttributeMaxDynamicSharedMemorySize, SMEM_GCN);

    wsplit_kernel<<<80, 256>>>(g1_w, g2_w, g3_w, wfh, wfl);
    embed_kernel<<<GB, 256>>>(obs, e1_w, e1_b, e2_w, e2_b, bufB);
    gcn_mma_kernel<64,  false><<<GB, 256, SMEM_GCN>>>(bufB, wfh,         wfl,         g1_b, bufA, nullptr);
    gcn_mma_kernel<128, false><<<GB, 256, SMEM_GCN>>>(bufA, wfh + 4096,  wfl + 4096,  g2_b, bufB, nullptr);
    gcn_mma_kernel<128, true ><<<GB, 256, SMEM_GCN>>>(bufB, wfh + 12288, wfl + 12288, g3_b, nullptr, part);
    readout_kernel<<<B_, 256>>>(part, r1_w, r1_b, r2_w, r2_b, out);
}

// round 10
// speedup vs baseline: 2.1859x; 1.1279x over previous
#include <cuda_runtime.h>
#include <cuda_bf16.h>
#include <cstdint>

// ---------------------------------------------------------------------------
// GNNRepresentationNetwork  B=16, C=16, N=4096 (64x64), D_E=64, D_H=128, D_R=256
// embed: FFMA2 fused MLP (fp32 exact), W2 fully resident, 2 syncs.
// GCN: mma.sync m16n8k16 bf16, 3-pass split (D = Ah*Bh + Ah*Bl + Al*Bh).
//   - W pre-split to fragment-order global buffers; A-frags via __ldg -> regs
//   - triple-buffered cp.async halo windows, slice-interleaved MMA (per 16-k)
// GCN identity (exact): relu(A(hW+b)) = relu((A h)W + s_n b), s_n = deg/(deg+1e-6)
// ---------------------------------------------------------------------------

#define B_  16
#define N_  4096

typedef unsigned long long u64;

__device__ float g_bufA[B_ * 128 * N_];
__device__ float g_bufB[B_ * 128 * N_];
__device__ float g_part[B_ * 64 * 128];      // 512 blocks x 2 halves x 128 d
__device__ uint32_t g_wfh[20480];            // W frags hi: g1[0,4096) g2[4096,12288) g3[12288,20480)
__device__ uint32_t g_wfl[20480];            // W frags lo

__device__ __forceinline__ void fma2(u64& d, u64 a, u64 b) {
    asm("fma.rn.f32x2 %0, %1, %2, %0;" : "+l"(d) : "l"(a), "l"(b));
}
__device__ __forceinline__ u64 pack2(float lo, float hi) {
    u64 r; asm("mov.b64 %0, {%1, %2};" : "=l"(r) : "f"(lo), "f"(hi)); return r;
}
__device__ __forceinline__ float2 unpack2(u64 v) {
    float2 f; asm("mov.b64 {%0, %1}, %2;" : "=f"(f.x), "=f"(f.y) : "l"(v)); return f;
}
__device__ __forceinline__ float recip_deg(int deg) {
    return deg == 4 ? 0.2499999375f : (deg == 3 ? 0.3333332222f : 0.4999997500f);
}
__device__ __forceinline__ uint32_t pack_bf16(__nv_bfloat16 a, __nv_bfloat16 b) {
    return (uint32_t)__bfloat16_as_ushort(a) | ((uint32_t)__bfloat16_as_ushort(b) << 16);
}
__device__ __forceinline__ void mma_bf16(float* c, const uint32_t* a, uint32_t b0, uint32_t b1) {
    asm volatile(
        "mma.sync.aligned.m16n8k16.row.col.f32.bf16.bf16.f32 "
        "{%0,%1,%2,%3}, {%4,%5,%6,%7}, {%8,%9}, {%0,%1,%2,%3};"
        : "+f"(c[0]), "+f"(c[1]), "+f"(c[2]), "+f"(c[3])
        : "r"(a[0]), "r"(a[1]), "r"(a[2]), "r"(a[3]), "r"(b0), "r"(b1));
}
__device__ __forceinline__ void cp16(uint32_t daddr, const void* g, int sz) {
    asm volatile("cp.async.cg.shared.global [%0], [%1], 16, %2;"
                 :: "r"(daddr), "l"(g), "r"(sz) : "memory");
}
#define CP_COMMIT() asm volatile("cp.async.commit_group;" ::: "memory")
#define CP_WAIT0()  asm volatile("cp.async.wait_group 0;" ::: "memory")
#define CP_WAIT1()  asm volatile("cp.async.wait_group 1;" ::: "memory")

// ---------------------------------------------------------------------------
// Pre-kernel: split the 3 GCN weight matrices into bf16 hi/lo A-fragment order.
// Word layout per 64-K chunk (4096 words): [wq(4)][t(2)][ks(4)][lane(32)][j(4)]
// ---------------------------------------------------------------------------
__global__ void __launch_bounds__(256)
wsplit_kernel(const float* __restrict__ g1w, const float* __restrict__ g2w,
              const float* __restrict__ g3w, uint32_t* __restrict__ wfh,
              uint32_t* __restrict__ wfl)
{
    const int idx = blockIdx.x * 256 + threadIdx.x;     // 0..20479
    const float* W; int base;
    if (idx < 4096)       { W = g1w; base = 0; }
    else if (idx < 12288) { W = g2w; base = 4096; }
    else                  { W = g3w; base = 12288; }
    const int r = idx - base;
    const int chunk = r >> 12;
    const int w = r & 4095;
    const int lane4 = w & 127, ksI = (w >> 7) & 3, t = (w >> 9) & 1, wq = (w >> 10) & 3;
    const int lane = lane4 >> 2, j = lane4 & 3;
    const int grp = lane >> 2, tig = lane & 3;
    const int d = wq * 32 + t * 16 + grp + (j & 1) * 8;
    const int kg = chunk * 64 + ksI * 16 + tig * 2 + (j >> 1) * 8;
    const float w0 = W[kg * 128 + d];
    const float w1 = W[(kg + 1) * 128 + d];
    const __nv_bfloat16 h0 = __float2bfloat16(w0);
    const __nv_bfloat16 l0 = __float2bfloat16(w0 - __bfloat162float(h0));
    const __nv_bfloat16 h1 = __float2bfloat16(w1);
    const __nv_bfloat16 l1 = __float2bfloat16(w1 - __bfloat162float(h1));
    wfh[idx] = pack_bf16(h0, h1);
    wfl[idx] = pack_bf16(l0, l1);
}

// ---------------------------------------------------------------------------
// GCN layer. Per CTA: D(128d x 128n). 8 warps: wq=wid&3 -> 32 d, nh=wid>>2 -> 64 n.
// smem bytes: scp[0,512) | Ls 3x16x256 f32 [512,49664) | Sh[49664,66560) | Sl[66560,83456)
//   S frag word offset: (c*4+ks)*66 + (n&7)*8 + idx, idx = kb<8 ? kb : kb-7
// ---------------------------------------------------------------------------
#define SMEM_GCN 83456

__device__ __forceinline__ void issue_window(uint32_t LsBufA, const float* inb,
                                             int kbase, int n0, int tid)
{
#pragma unroll
    for (int i = 0; i < 4; i++) {
        const int idx = i * 256 + tid;
        const int r = idx >> 6, c4 = idx & 63;
        const int nw = n0 - 64 + c4 * 4;
        const bool v = (nw >= 0) && (nw < N_);
        const float* g = v ? (inb + (size_t)(kbase + r) * N_ + nw) : inb;
        cp16(LsBufA + (uint32_t)((r * 256 + c4 * 4) * 4), g, v ? 16 : 0);
    }
}

template <int K, bool MEAN>
__global__ void __launch_bounds__(256, 2)
gcn_mma_kernel(const float* __restrict__ in,
               const uint32_t* __restrict__ wfh, const uint32_t* __restrict__ wfl,
               const float* __restrict__ bias, float* __restrict__ out,
               float* __restrict__ part)
{
    extern __shared__ __align__(16) char smem[];
    float*    scp = reinterpret_cast<float*>(smem);
    float*    Ls  = reinterpret_cast<float*>(smem + 512);
    uint32_t* Sh  = reinterpret_cast<uint32_t*>(smem + 49664);
    uint32_t* Sl  = Sh + 4224;

    uint32_t sb;
    asm("{ .reg .u64 t; cvta.to.shared.u64 t, %1; cvt.u32.u64 %0, t; }" : "=r"(sb) : "l"(smem));
    const uint32_t LsA = sb + 512;

    const int tid = threadIdx.x;
    const int wid = tid >> 5, lane = tid & 31;
    const int grp = lane >> 2, tig = lane & 3;
    const int wq = wid & 3, nh = wid >> 2;
    const int m0 = blockIdx.x * 128;
    const int b  = m0 >> 12, n0 = m0 & (N_ - 1);
    const float* inb = in + (size_t)b * K * N_;

    if (tid < 128) {
        const int nn = n0 + tid;
        const int gi = nn >> 6, gj = nn & 63;
        const float fd = (float)((gi > 0) + (gi < 63) + (gj > 0) + (gj < 63));
        scp[tid] = fd / (fd + 1e-6f);
    }

    // S-build constants: thread handles k-pair kp (2 k) x 4 n starting at n4
    const int kp = tid >> 5;
    const int n4 = (tid & 31) * 4;
    const int gi2 = (n0 + n4) >> 6;
    const int dm  = (gi2 > 0) + (gi2 < 63);
    const bool lv0 = (n4 & 63) != 0;
    const bool rv3 = ((n4 + 3) & 63) != 63;
    const float rd0  = recip_deg(dm + (lv0 ? 1 : 0) + 1);
    const float rd12 = recip_deg(dm + 2);
    const float rd3  = recip_deg(dm + 1 + (rv3 ? 1 : 0));
    const int kb  = kp * 2;
    const int sidx = kb < 8 ? kb : kb - 7;
    const int rowc = (n4 >> 3) * 4;            // c-row base
    const int rowo = sidx + (n4 & 7) * 8;      // within-row word base

    float acc[2][8][4];
#pragma unroll
    for (int t = 0; t < 2; t++)
#pragma unroll
        for (int c = 0; c < 8; c++)
#pragma unroll
            for (int j = 0; j < 4; j++) acc[t][c][j] = 0.f;

    constexpr int TOTW = K / 16;               // 16-k windows total
    // Prologue: two windows in flight
    issue_window(LsA, inb, 0, n0, tid);
    CP_COMMIT();
    issue_window(LsA + 16384, inb, 16, n0, tid);
    CP_COMMIT();

    for (int wg = 0; wg < TOTW; wg++) {
        if (wg + 1 < TOTW) { CP_WAIT1(); } else { CP_WAIT0(); }
        __syncthreads();

        if (wg + 2 < TOTW) {
            issue_window(LsA + (uint32_t)(((wg + 2) % 3) * 16384), inb,
                         (wg + 2) * 16, n0, tid);
            CP_COMMIT();
        }

        // A-fragments for this slice straight from L2 (shared across all CTAs)
        const int chunk = wg >> 2, ks = wg & 3;
        uint32_t ah[2][4], al[2][4];
#pragma unroll
        for (int t = 0; t < 2; t++) {
            const int fo = chunk * 4096 + ((wq * 2 + t) * 4 + ks) * 128 + lane * 4;
            const uint4 vh = __ldg(reinterpret_cast<const uint4*>(&wfh[fo]));
            const uint4 vl = __ldg(reinterpret_cast<const uint4*>(&wfl[fo]));
            ah[t][0] = vh.x; ah[t][1] = vh.y; ah[t][2] = vh.z; ah[t][3] = vh.w;
            al[t][0] = vl.x; al[t][1] = vl.y; al[t][2] = vl.z; al[t][3] = vl.w;
        }

        // Build S(ks) from window buffer wg%3: 2 k x 4 n per thread
        {
            const float* Lb = Ls + (wg % 3) * 4096;
            float o[2][4];
#pragma unroll
            for (int e = 0; e < 2; e++) {
                const float* L = Lb + (kp * 2 + e) * 256 + n4;
                const float4 up = *reinterpret_cast<const float4*>(L);
                const float4 ct = *reinterpret_cast<const float4*>(L + 64);
                const float4 dn = *reinterpret_cast<const float4*>(L + 128);
                const float lf = lv0 ? L[63] : 0.f;
                const float rt = rv3 ? L[68] : 0.f;
                o[e][0] = (up.x + dn.x + lf   + ct.y) * rd0;
                o[e][1] = (up.y + dn.y + ct.x + ct.z) * rd12;
                o[e][2] = (up.z + dn.z + ct.y + ct.w) * rd12;
                o[e][3] = (up.w + dn.w + ct.z + rt  ) * rd3;
            }
            const int wbase = (rowc + ks) * 66 + rowo;
#pragma unroll
            for (int i = 0; i < 4; i++) {
                const __nv_bfloat16 h0 = __float2bfloat16(o[0][i]);
                const __nv_bfloat16 h1 = __float2bfloat16(o[1][i]);
                const __nv_bfloat16 l0 = __float2bfloat16(o[0][i] - __bfloat162float(h0));
                const __nv_bfloat16 l1 = __float2bfloat16(o[1][i] - __bfloat162float(h1));
                Sh[wbase + i * 8] = pack_bf16(h0, h1);
                Sl[wbase + i * 8] = pack_bf16(l0, l1);
            }
        }
        __syncthreads();

        // MMA slice for this 16-k window
#pragma unroll
        for (int c = 0; c < 8; c++) {
            const int cg = nh * 8 + c;
            const uint2 bh = *reinterpret_cast<const uint2*>(&Sh[(cg * 4 + ks) * 66 + lane * 2]);
            const uint2 bl = *reinterpret_cast<const uint2*>(&Sl[(cg * 4 + ks) * 66 + lane * 2]);
            mma_bf16(acc[0][c], ah[0], bh.x, bh.y);
            mma_bf16(acc[0][c], ah[0], bl.x, bl.y);
            mma_bf16(acc[0][c], al[0], bh.x, bh.y);
            mma_bf16(acc[1][c], ah[1], bh.x, bh.y);
            mma_bf16(acc[1][c], ah[1], bl.x, bl.y);
            mma_bf16(acc[1][c], al[1], bh.x, bh.y);
        }
    }

    // --- Epilogue: scaled bias + relu ---
    const int d0 = wq * 32 + grp;
    const float bv[4] = { __ldg(&bias[d0]),      __ldg(&bias[d0 + 8]),
                          __ldg(&bias[d0 + 16]), __ldg(&bias[d0 + 24]) };

    if (!MEAN) {
        float* ob = out + (size_t)b * 128 * N_ + n0;
#pragma unroll
        for (int t = 0; t < 2; t++) {
            float* r0 = ob + (size_t)(d0 + t * 16) * N_;
            float* r1 = r0 + (size_t)8 * N_;
#pragma unroll
            for (int c = 0; c < 8; c++) {
                const int nn = nh * 64 + c * 8 + tig * 2;
                const float s0 = scp[nn], s1 = scp[nn + 1];
                float2 v0, v1;
                v0.x = fmaxf(fmaf(s0, bv[t * 2], acc[t][c][0]), 0.f);
                v0.y = fmaxf(fmaf(s1, bv[t * 2], acc[t][c][1]), 0.f);
                v1.x = fmaxf(fmaf(s0, bv[t * 2 + 1], acc[t][c][2]), 0.f);
                v1.y = fmaxf(fmaf(s1, bv[t * 2 + 1], acc[t][c][3]), 0.f);
                *reinterpret_cast<float2*>(r0 + nn) = v0;
                *reinterpret_cast<float2*>(r1 + nn) = v1;
            }
        }
    } else {
        float sums[4] = { 0.f, 0.f, 0.f, 0.f };
#pragma unroll
        for (int t = 0; t < 2; t++)
#pragma unroll
            for (int c = 0; c < 8; c++) {
                const int nn = nh * 64 + c * 8 + tig * 2;
                const float s0 = scp[nn], s1 = scp[nn + 1];
                sums[t * 2]     += fmaxf(fmaf(s0, bv[t * 2], acc[t][c][0]), 0.f)
                                 + fmaxf(fmaf(s1, bv[t * 2], acc[t][c][1]), 0.f);
                sums[t * 2 + 1] += fmaxf(fmaf(s0, bv[t * 2 + 1], acc[t][c][2]), 0.f)
                                 + fmaxf(fmaf(s1, bv[t * 2 + 1], acc[t][c][3]), 0.f);
            }
#pragma unroll
        for (int q = 0; q < 4; q++) {
            sums[q] += __shfl_xor_sync(0xffffffffu, sums[q], 1);
            sums[q] += __shfl_xor_sync(0xffffffffu, sums[q], 2);
        }
        if (tig == 0) {
            float* pp = part + ((size_t)blockIdx.x * 2 + nh) * 128;
            pp[d0]      = sums[0];
            pp[d0 + 8]  = sums[1];
            pp[d0 + 16] = sums[2];
            pp[d0 + 24] = sums[3];
        }
    }
}

// ---------------------------------------------------------------------------
// Fused embed MLP (FFMA2): out = relu(relu(x W1 + b1) W2 + b2)
// W1 + full W2 resident in smem; 2 syncs total. 60 KB dyn smem -> 3 CTAs/SM.
// smem floats: Xs[0,2048) W1s[2048,3072) W2s[3072,7168) Hs[7168,15360)
// ---------------------------------------------------------------------------
#define SMEM_EMB 61440

__global__ void __launch_bounds__(256, 3)
embed_kernel(const float* __restrict__ obs,
             const float* __restrict__ w1, const float* __restrict__ b1,
             const float* __restrict__ w2, const float* __restrict__ b2,
             float* __restrict__ out)
{
    extern __shared__ __align__(16) float esm[];
    float* Xs  = esm;
    float* W1s = esm + 2048;
    float* W2s = esm + 3072;
    float* Hs  = esm + 7168;

    uint32_t sb;
    asm("{ .reg .u64 t; cvta.to.shared.u64 t, %1; cvt.u32.u64 %0, t; }" : "=r"(sb) : "l"(esm));

    const int tid = threadIdx.x, tx = tid & 15, ty = tid >> 4;
    const int m0 = blockIdx.x * 128;
    const int b  = m0 >> 12, n0 = m0 & (N_ - 1);
    const float* xb = obs + (size_t)b * 16 * N_ + n0;

    // Stage X tile (512 f4), W1 (256 f4), W2 (1024 f4) via cp.async
    {
        const int i0 = tid, i1 = tid + 256;
        cp16(sb + (uint32_t)(((i0 >> 5) * 128 + (i0 & 31) * 4) * 4),
             reinterpret_cast<const float4*>(xb + (size_t)(i0 >> 5) * N_) + (i0 & 31), 16);
        cp16(sb + (uint32_t)(((i1 >> 5) * 128 + (i1 & 31) * 4) * 4),
             reinterpret_cast<const float4*>(xb + (size_t)(i1 >> 5) * N_) + (i1 & 31), 16);
        cp16(sb + (uint32_t)((2048 + tid * 4) * 4), reinterpret_cast<const float4*>(w1) + tid, 16);
#pragma unroll
        for (int i = 0; i < 4; i++)
            cp16(sb + (uint32_t)((3072 + (i * 256 + tid) * 4) * 4),
                 reinterpret_cast<const float4*>(w2) + i * 256 + tid, 16);
    }
    CP_COMMIT();
    CP_WAIT0();
    __syncthreads();

    // Layer 1: acc[4 d][4 n-pairs], K=16
    u64 acc[4][4];
#pragma unroll
    for (int dd = 0; dd < 4; dd++) {
        const float bv = b1[ty * 4 + dd];
        const u64 bp = pack2(bv, bv);
#pragma unroll
        for (int j = 0; j < 4; j++) acc[dd][j] = bp;
    }
#pragma unroll
    for (int k = 0; k < 16; k++) {
        const ulonglong2 a01 = *reinterpret_cast<const ulonglong2*>(&Xs[k * 128 + tx * 8]);
        const ulonglong2 a23 = *reinterpret_cast<const ulonglong2*>(&Xs[k * 128 + tx * 8 + 4]);
        const u64 a[4] = { a01.x, a01.y, a23.x, a23.y };
        const float4 w = *reinterpret_cast<const float4*>(&W1s[k * 64 + ty * 4]);
        const float wv[4] = { w.x, w.y, w.z, w.w };
#pragma unroll
        for (int dd = 0; dd < 4; dd++) {
            const u64 wd = pack2(wv[dd], wv[dd]);
#pragma unroll
            for (int j = 0; j < 4; j++) fma2(acc[dd][j], wd, a[j]);
        }
    }
#pragma unroll
    for (int dd = 0; dd < 4; dd++) {
        float* hr = &Hs[(ty * 4 + dd) * 128 + tx * 8];
#pragma unroll
        for (int j = 0; j < 4; j += 2) {
            const float2 p0 = unpack2(acc[dd][j]), p1 = unpack2(acc[dd][j + 1]);
            float4 o = { fmaxf(p0.x, 0.f), fmaxf(p0.y, 0.f), fmaxf(p1.x, 0.f), fmaxf(p1.y, 0.f) };
            *reinterpret_cast<float4*>(hr + j * 2) = o;
        }
    }
    __syncthreads();

    // Layer 2: K=64, W2 fully resident, no more syncs
    u64 acc2[4][4];
#pragma unroll
    for (int dd = 0; dd < 4; dd++) {
        const float bv = b2[ty * 4 + dd];
        const u64 bp = pack2(bv, bv);
#pragma unroll
        for (int j = 0; j < 4; j++) acc2[dd][j] = bp;
    }
#pragma unroll 4
    for (int k = 0; k < 64; k++) {
        const ulonglong2 a01 = *reinterpret_cast<const ulonglong2*>(&Hs[k * 128 + tx * 8]);
        const ulonglong2 a23 = *reinterpret_cast<const ulonglong2*>(&Hs[k * 128 + tx * 8 + 4]);
        const u64 a[4] = { a01.x, a01.y, a23.x, a23.y };
        const float4 w = *reinterpret_cast<const float4*>(&W2s[k * 64 + ty * 4]);
        const float wv[4] = { w.x, w.y, w.z, w.w };
#pragma unroll
        for (int dd = 0; dd < 4; dd++) {
            const u64 wd = pack2(wv[dd], wv[dd]);
#pragma unroll
            for (int j = 0; j < 4; j++) fma2(acc2[dd][j], wd, a[j]);
        }
    }

    float* ob = out + (size_t)b * 64 * N_ + n0 + tx * 8;
#pragma unroll
    for (int dd = 0; dd < 4; dd++) {
        float* orow = ob + (size_t)(ty * 4 + dd) * N_;
#pragma unroll
        for (int j = 0; j < 4; j += 2) {
            const float2 p0 = unpack2(acc2[dd][j]), p1 = unpack2(acc2[dd][j + 1]);
            float4 o = { fmaxf(p0.x, 0.f), fmaxf(p0.y, 0.f), fmaxf(p1.x, 0.f), fmaxf(p1.y, 0.f) };
            *reinterpret_cast<float4*>(orow + j * 2) = o;
        }
    }
}

// ---------------------------------------------------------------------------
// Readout: g[b] = mean of 64 partials; out = relu(relu(g r1 + b1) r2 + b2)
// ---------------------------------------------------------------------------
__global__ void __launch_bounds__(256)
readout_kernel(const float* __restrict__ part,
               const float* __restrict__ r1w, const float* __restrict__ r1b,
               const float* __restrict__ r2w, const float* __restrict__ r2b,
               float* __restrict__ out)
{
    __shared__ float gs[128];
    __shared__ float ts[256];
    const int b = blockIdx.x, t = threadIdx.x;

    if (t < 128) {
        float s = 0.f;
        const float* p = part + (size_t)b * 64 * 128 + t;
#pragma unroll
        for (int k = 0; k < 64; k++) s += p[k * 128];
        gs[t] = s * (1.0f / (float)N_);
    }
    __syncthreads();

    float a1 = r1b[t];
#pragma unroll 8
    for (int k = 0; k < 128; k++) a1 = fmaf(gs[k], r1w[k * 256 + t], a1);
    ts[t] = fmaxf(a1, 0.f);
    __syncthreads();

    float a2 = r2b[t];
#pragma unroll 8
    for (int k = 0; k < 256; k++) a2 = fmaf(ts[k], r2w[k * 256 + t], a2);
    out[b * 256 + t] = fmaxf(a2, 0.f);
}

// ---------------------------------------------------------------------------
extern "C" void kernel_launch(void* const* d_in, const int* in_sizes, int n_in,
                              void* d_out, int out_size)
{
    const float* obs  = (const float*)d_in[0];
    const float* e1_w = (const float*)d_in[1];
    const float* e1_b = (const float*)d_in[2];
    const float* e2_w = (const float*)d_in[3];
    const float* e2_b = (const float*)d_in[4];
    const float* g1_w = (const float*)d_in[5];
    const float* g1_b = (const float*)d_in[6];
    const float* g2_w = (const float*)d_in[7];
    const float* g2_b = (const float*)d_in[8];
    const float* g3_w = (const float*)d_in[9];
    const float* g3_b = (const float*)d_in[10];
    const float* r1_w = (const float*)d_in[11];
    const float* r1_b = (const float*)d_in[12];
    const float* r2_w = (const float*)d_in[13];
    const float* r2_b = (const float*)d_in[14];
    float* out = (float*)d_out;

    float *bufA, *bufB, *part;
    uint32_t *wfh, *wfl;
    cudaGetSymbolAddress((void**)&bufA, g_bufA);
    cudaGetSymbolAddress((void**)&bufB, g_bufB);
    cudaGetSymbolAddress((void**)&part, g_part);
    cudaGetSymbolAddress((void**)&wfh,  g_wfh);
    cudaGetSymbolAddress((void**)&wfl,  g_wfl);

    const int GB = (B_ * N_) / 128;   // 512 blocks

    cudaFuncSetAttribute(gcn_mma_kernel<64,  false>, cudaFuncAttributeMaxDynamicSharedMemorySize, SMEM_GCN);
    cudaFuncSetAttribute(gcn_mma_kernel<128, false>, cudaFuncAttributeMaxDynamicSharedMemorySize, SMEM_GCN);
    cudaFuncSetAttribute(gcn_mma_kernel<128, true >, cudaFuncAttributeMaxDynamicSharedMemorySize, SMEM_GCN);
    cudaFuncSetAttribute(embed_kernel, cudaFuncAttributeMaxDynamicSharedMemorySize, SMEM_EMB);

    wsplit_kernel<<<80, 256>>>(g1_w, g2_w, g3_w, wfh, wfl);
    embed_kernel<<<GB, 256, SMEM_EMB>>>(obs, e1_w, e1_b, e2_w, e2_b, bufB);
    gcn_mma_kernel<64,  false><<<GB, 256, SMEM_GCN>>>(bufB, wfh,         wfl,         g1_b, bufA, nullptr);
    gcn_mma_kernel<128, false><<<GB, 256, SMEM_GCN>>>(bufA, wfh + 4096,  wfl + 4096,  g2_b, bufB, nullptr);
    gcn_mma_kernel<128, true ><<<GB, 256, SMEM_GCN>>>(bufB, wfh + 12288, wfl + 12288, g3_b, nullptr, part);
    readout_kernel<<<B_, 256>>>(part, r1_w, r1_b, r2_w, r2_b, out);
}